// round 12
// baseline (speedup 1.0000x reference)
#include <cuda_runtime.h>
#include <cstdint>

// Problem constants
#define BB 8
#define LL 4096
#define DD 768
#define NROWS (BB * LL)        // 32768
#define NB 1024                // blocks; 148 SMs x 8 co-resident slots = 1184 >= NB
#define NT 128                 // 4 warps
#define RPW 8                  // rows per warp (phase 1): 1024*4*8 = 32768 exact

// Scratch (device globals). No cache hints (R2/R3/R8 all failed).
__device__ __align__(16) float g_part[NB * DD];    // per-block column partials (3 MB)
__device__ __align__(16) float g_sum[BB * DD];     // full column sums
__device__ float g_sqpart[BB * 6];                 // per-colgroup sum of squares
__device__ unsigned g_arrive = 0;                  // epoch barrier (monotone, replay-safe)

__device__ __forceinline__ void grid_barrier() {
    __syncthreads();
    if (threadIdx.x == 0) {
        __threadfence();
        unsigned old = atomicAdd(&g_arrive, 1u);
        unsigned target = (old / NB + 1u) * NB;
        while ((int)(*(volatile unsigned*)&g_arrive - target) < 0)
            __nanosleep(32);
    }
    __syncthreads();
}

__global__ __launch_bounds__(NT, 8) void fused_kernel(const float* __restrict__ x,
                                                      const float* __restrict__ alpha,
                                                      float* __restrict__ out) {
    __shared__ float4 s_acc[4][DD / 4];   // 12 KB: per-warp column partials (phase 1)
    __shared__ float red[NT];             // phase 2 reduce

    const int tid  = threadIdx.x;
    const int bid  = blockIdx.x;
    const int warp = tid >> 5;
    const int lane = tid & 31;

    // ---- Phase 1: column sums. One warp = exactly 8 rows; one block = 32 rows
    // (one batch spans 128 consecutive blocks). Perfectly balanced, no atomics.
    {
        const size_t rowbase = (size_t)bid * 32 + warp * RPW;
        const float4* xp = reinterpret_cast<const float4*>(x) + rowbase * (DD / 4) + lane;

        float4 acc[6];
#pragma unroll
        for (int i = 0; i < 6; i++) acc[i] = make_float4(0.f, 0.f, 0.f, 0.f);
#pragma unroll
        for (int r = 0; r < RPW; r++) {
#pragma unroll
            for (int i = 0; i < 6; i++) {
                float4 v = xp[(size_t)r * (DD / 4) + i * 32];
                acc[i].x += v.x; acc[i].y += v.y; acc[i].z += v.z; acc[i].w += v.w;
            }
        }
#pragma unroll
        for (int i = 0; i < 6; i++) s_acc[warp][lane + i * 32] = acc[i];
        __syncthreads();

        // 128 threads reduce 4 warp-partials x 768 cols (6 cols/thread)
        const float* sa = reinterpret_cast<const float*>(s_acc);
#pragma unroll
        for (int k = 0; k < 6; k++) {
            const int col = tid + k * NT;
            float s = (sa[0 * DD + col] + sa[1 * DD + col])
                    + (sa[2 * DD + col] + sa[3 * DD + col]);
            g_part[(size_t)bid * DD + col] = s;
        }
    }

    grid_barrier();

    // ---- Phase 2: 48 blocks (8 batches x 6 col-groups of 128). Reduce the 128
    // block-partials of each batch; also per-group sum of squares (~3 MB, L2).
    if (bid < 48) {
        const int b = bid / 6;
        const int g = bid % 6;
        const int col = g * NT + tid;

        const float* p = g_part + (size_t)b * 128 * DD + col;
        float a0 = 0.f, a1 = 0.f, a2 = 0.f, a3 = 0.f;
#pragma unroll 8
        for (int k = 0; k < 128; k += 4) {
            a0 += p[(size_t)(k + 0) * DD];
            a1 += p[(size_t)(k + 1) * DD];
            a2 += p[(size_t)(k + 2) * DD];
            a3 += p[(size_t)(k + 3) * DD];
        }
        const float s = (a0 + a1) + (a2 + a3);
        g_sum[b * DD + col] = s;

        red[tid] = s * s;
        __syncthreads();
        if (tid < 64) red[tid] += red[tid + 64];
        __syncthreads();
        if (tid < 32) {
            float v = red[tid] + red[tid + 32];
#pragma unroll
            for (int off = 16; off > 0; off >>= 1)
                v += __shfl_xor_sync(0xFFFFFFFFu, v, off);
            if (tid == 0) g_sqpart[b * 6 + g] = v;
        }
    }

    grid_barrier();

    // ---- Phase 3: finalize, batches DESCENDING, sync-free.
    // wg = global warp id (0..4095), l = 4095 - wg fixed per warp; iteration j
    // covers exactly batch 7-j across all 4096 warps — the coherent 12 MB
    // frontier that keeps the second x read in L2 (~75-85 MB saved, measured
    // R6/R9/R10/R11). sum_b/coef read per-warp from global (L1/L2-hot).
    {
        const int wg = bid * 4 + warp;          // 0..4095
        const int l  = 4095 - wg;
        const float a = alpha[l];
        const double denom = (double)DD * (double)DD
                           * (double)LL * (double)LL * (double)LL * (double)LL;
        const float4* gsum4 = reinterpret_cast<const float4*>(g_sum);

#pragma unroll 1
        for (int j = 0; j < 8; j++) {
            const int b = 7 - j;
            const float sq = (g_sqpart[b * 6 + 0] + g_sqpart[b * 6 + 1])
                           + (g_sqpart[b * 6 + 2] + g_sqpart[b * 6 + 3])
                           + (g_sqpart[b * 6 + 4] + g_sqpart[b * 6 + 5]);
            const float coef = (float)((double)sq / denom);

            const int row = (b << 12) | l;
            const float4* xp = reinterpret_cast<const float4*>(x + (size_t)row * DD);
            const float4* mp = gsum4 + b * (DD / 4);
            float4 v[6];
            float dot = 0.f;
#pragma unroll
            for (int i = 0; i < 6; i++) {
                v[i] = xp[lane + i * 32];
                float4 m = mp[lane + i * 32];
                dot += v[i].x * m.x + v[i].y * m.y + v[i].z * m.z + v[i].w * m.w;
            }
#pragma unroll
            for (int off = 16; off > 0; off >>= 1)
                dot += __shfl_xor_sync(0xFFFFFFFFu, dot, off);

            const float y2 = dot * coef;

            float4* op = reinterpret_cast<float4*>(out + (size_t)row * DD);
#pragma unroll
            for (int i = 0; i < 6; i++) {
                float4 o;
                o.x = a + y2 * v[i].x;
                o.y = a + y2 * v[i].y;
                o.z = a + y2 * v[i].z;
                o.w = a + y2 * v[i].w;
                op[lane + i * 32] = o;
            }
        }
    }
}

extern "C" void kernel_launch(void* const* d_in, const int* in_sizes, int n_in,
                              void* d_out, int out_size) {
    const float* x     = (const float*)d_in[0];   // [8, 4096, 768] f32
    const float* alpha = (const float*)d_in[1];   // [4096, 1] f32
    float* out = (float*)d_out;                   // [8, 4096, 768] f32

    fused_kernel<<<NB, NT>>>(x, alpha, out);
}